// round 11
// baseline (speedup 1.0000x reference)
#include <cuda_runtime.h>
#include <cuda_bf16.h>

// Sorted segment-sum: feat [N,128] f32, segment_ids [N] i32 (non-decreasing),
// out [4096,128] f32.
//
// R10 changes vs R7 (85.6us total / 82.8us kernel, DRAM 79.6%, occ 87.6%):
//  - dynamic work-stealing: persistent grid (152 SMs x 8 blocks), each WARP
//    pulls 64-row tickets from a global atomic counter. ~15.6K tickets
//    (~105/SM, ~0.8us granularity) absorb the between-SM spread floor
//    (L2 near/far die variance) that static assignment pays as idle tail.
//  - counter reset via 4-byte cudaMemsetAsync on a __device__ symbol
//    (cudaGetSymbolAddress — no allocation).
// Hot loop body unchanged from R7 (regs must stay at 32 for 8 blocks/SM).

#define D_FEAT 128
#define LANES_F4 (D_FEAT / 4)      // 32 float4 per row == 32 lanes
#define CHUNK_ROWS 64
#define THREADS_PER_BLOCK 256
#define WARPS_PER_BLOCK (THREADS_PER_BLOCK / 32)
#define PERSISTENT_BLOCKS (152 * 8)   // GB300: 152 SMs, 8 CTAs/SM at regs<=32

__device__ int g_ticket;

__device__ __forceinline__ void red_flush(float* __restrict__ out, int segid,
                                          int lane, float4& acc) {
    float* dst = out + (size_t)segid * D_FEAT + lane * 4;   // 16B aligned
    asm volatile("red.global.add.v4.f32 [%0], {%1, %2, %3, %4};"
                 :: "l"(dst), "f"(acc.x), "f"(acc.y), "f"(acc.z), "f"(acc.w)
                 : "memory");
    acc = make_float4(0.f, 0.f, 0.f, 0.f);
}

__global__ __launch_bounds__(THREADS_PER_BLOCK, 8)
void segment_sum_kernel(const float4* __restrict__ feat4,
                        const int* __restrict__ seg,
                        float* __restrict__ out,
                        int n_rows, int n_chunks) {
    const int lane = threadIdx.x & 31;

    for (;;) {
        int c = 0;
        if (lane == 0) c = atomicAdd(&g_ticket, 1);
        c = __shfl_sync(0xffffffffu, c, 0);
        if (c >= n_chunks) return;

        int row0 = c * CHUNK_ROWS;
        int row_end = row0 + CHUNK_ROWS;
        if (row_end > n_rows) row_end = n_rows;

        float4 acc = make_float4(0.f, 0.f, 0.f, 0.f);
        int cur = __ldg(seg + row0);

        int r = row0;
        while (r < row_end) {
            if (r + 8 <= row_end && __ldg(seg + r + 7) == cur) {
                // Fast path: all 8 rows in segment `cur`. 8 independent
                // evict-first loads (read-once stream).
                const float4* p = feat4 + (size_t)r * LANES_F4 + lane;
                float4 v0 = __ldcs(p + 0 * LANES_F4);
                float4 v1 = __ldcs(p + 1 * LANES_F4);
                float4 v2 = __ldcs(p + 2 * LANES_F4);
                float4 v3 = __ldcs(p + 3 * LANES_F4);
                float4 v4 = __ldcs(p + 4 * LANES_F4);
                float4 v5 = __ldcs(p + 5 * LANES_F4);
                float4 v6 = __ldcs(p + 6 * LANES_F4);
                float4 v7 = __ldcs(p + 7 * LANES_F4);
                // pairwise tree to shorten the dependent-add chain
                float4 s01, s23, s45, s67, s03, s47;
                s01.x = v0.x + v1.x; s01.y = v0.y + v1.y; s01.z = v0.z + v1.z; s01.w = v0.w + v1.w;
                s23.x = v2.x + v3.x; s23.y = v2.y + v3.y; s23.z = v2.z + v3.z; s23.w = v2.w + v3.w;
                s45.x = v4.x + v5.x; s45.y = v4.y + v5.y; s45.z = v4.z + v5.z; s45.w = v4.w + v5.w;
                s67.x = v6.x + v7.x; s67.y = v6.y + v7.y; s67.z = v6.z + v7.z; s67.w = v6.w + v7.w;
                s03.x = s01.x + s23.x; s03.y = s01.y + s23.y; s03.z = s01.z + s23.z; s03.w = s01.w + s23.w;
                s47.x = s45.x + s67.x; s47.y = s45.y + s67.y; s47.z = s45.z + s67.z; s47.w = s45.w + s67.w;
                acc.x += s03.x + s47.x;
                acc.y += s03.y + s47.y;
                acc.z += s03.z + s47.z;
                acc.w += s03.w + s47.w;
                r += 8;
            } else {
                // Slow path: segment boundary within the next 8 rows (or tail).
                int sid = __ldg(seg + r);
                if (sid != cur) {
                    red_flush(out, cur, lane, acc);
                    cur = sid;
                }
                float4 v = __ldcs(feat4 + (size_t)r * LANES_F4 + lane);
                acc.x += v.x; acc.y += v.y; acc.z += v.z; acc.w += v.w;
                r += 1;
            }
        }
        red_flush(out, cur, lane, acc);
    }
}

extern "C" void kernel_launch(void* const* d_in, const int* in_sizes, int n_in,
                              void* d_out, int out_size) {
    const float* feat = (const float*)d_in[0];
    const int* seg = (const int*)d_in[1];
    float* out = (float*)d_out;

    const int n_rows = in_sizes[1];            // segment_ids element count
    const int n_chunks = (n_rows + CHUNK_ROWS - 1) / CHUNK_ROWS;

    // 1) zero the (poisoned) output + reset the ticket counter (memset nodes)
    cudaMemsetAsync(out, 0, (size_t)out_size * sizeof(float));
    void* tick_ptr = nullptr;
    cudaGetSymbolAddress(&tick_ptr, g_ticket);
    cudaMemsetAsync(tick_ptr, 0, sizeof(int));

    // 2) persistent segment-sum with warp-level work stealing
    segment_sum_kernel<<<PERSISTENT_BLOCKS, THREADS_PER_BLOCK>>>(
        (const float4*)feat, seg, out, n_rows, n_chunks);
}

// round 12
// speedup vs baseline: 1.1189x; 1.1189x over previous
#include <cuda_runtime.h>
#include <cuda_bf16.h>

// Sorted segment-sum: feat [N,128] f32, segment_ids [N] i32 (non-decreasing),
// out [4096,128] f32.
//
// R11: hybrid static + stolen tail.
// R10's pure work-stealing regressed (1.6 tickets/warp -> 25% quantization).
// Here each of the 9728 persistent warps keeps an R7-style contiguous
// 96-row STATIC range (933,888 rows ~= 90% of work, zero scheduling
// overhead), then steals 16-row tickets from the remaining ~66K rows.
// ~4.1K tail tickets flow to early-finishing warps, absorbing the
// between-SM spread tail that R7 paid as idle time. Next-ticket prefetch
// hides the counter-atomic latency.

#define D_FEAT 128
#define LANES_F4 (D_FEAT / 4)      // 32 float4 per row == 32 lanes
#define THREADS_PER_BLOCK 256
#define WARPS_PER_BLOCK (THREADS_PER_BLOCK / 32)
#define PERSISTENT_BLOCKS (152 * 8)             // GB300: 152 SMs x 8 CTAs/SM
#define TOTAL_WARPS (PERSISTENT_BLOCKS * WARPS_PER_BLOCK)   // 9728
#define STATIC_ROWS 96
#define TAIL_CHUNK 16

__device__ int g_ticket;

__device__ __forceinline__ void red_flush(float* __restrict__ out, int segid,
                                          int lane, float4& acc) {
    float* dst = out + (size_t)segid * D_FEAT + lane * 4;   // 16B aligned
    asm volatile("red.global.add.v4.f32 [%0], {%1, %2, %3, %4};"
                 :: "l"(dst), "f"(acc.x), "f"(acc.y), "f"(acc.z), "f"(acc.w)
                 : "memory");
    acc = make_float4(0.f, 0.f, 0.f, 0.f);
}

// Process rows [row0, row_end) for this warp; identical hot body to R7.
__device__ __forceinline__ void process_range(const float4* __restrict__ feat4,
                                              const int* __restrict__ seg,
                                              float* __restrict__ out,
                                              int row0, int row_end, int lane) {
    float4 acc = make_float4(0.f, 0.f, 0.f, 0.f);
    int cur = __ldg(seg + row0);

    int r = row0;
    while (r < row_end) {
        if (r + 8 <= row_end && __ldg(seg + r + 7) == cur) {
            // Fast path: all 8 rows in segment `cur`. 8 independent
            // evict-first loads (read-once stream).
            const float4* p = feat4 + (size_t)r * LANES_F4 + lane;
            float4 v0 = __ldcs(p + 0 * LANES_F4);
            float4 v1 = __ldcs(p + 1 * LANES_F4);
            float4 v2 = __ldcs(p + 2 * LANES_F4);
            float4 v3 = __ldcs(p + 3 * LANES_F4);
            float4 v4 = __ldcs(p + 4 * LANES_F4);
            float4 v5 = __ldcs(p + 5 * LANES_F4);
            float4 v6 = __ldcs(p + 6 * LANES_F4);
            float4 v7 = __ldcs(p + 7 * LANES_F4);
            // pairwise tree to shorten the dependent-add chain
            float4 s01, s23, s45, s67, s03, s47;
            s01.x = v0.x + v1.x; s01.y = v0.y + v1.y; s01.z = v0.z + v1.z; s01.w = v0.w + v1.w;
            s23.x = v2.x + v3.x; s23.y = v2.y + v3.y; s23.z = v2.z + v3.z; s23.w = v2.w + v3.w;
            s45.x = v4.x + v5.x; s45.y = v4.y + v5.y; s45.z = v4.z + v5.z; s45.w = v4.w + v5.w;
            s67.x = v6.x + v7.x; s67.y = v6.y + v7.y; s67.z = v6.z + v7.z; s67.w = v6.w + v7.w;
            s03.x = s01.x + s23.x; s03.y = s01.y + s23.y; s03.z = s01.z + s23.z; s03.w = s01.w + s23.w;
            s47.x = s45.x + s67.x; s47.y = s45.y + s67.y; s47.z = s45.z + s67.z; s47.w = s45.w + s67.w;
            acc.x += s03.x + s47.x;
            acc.y += s03.y + s47.y;
            acc.z += s03.z + s47.z;
            acc.w += s03.w + s47.w;
            r += 8;
        } else {
            // Slow path: segment boundary within the next 8 rows (or tail).
            int sid = __ldg(seg + r);
            if (sid != cur) {
                red_flush(out, cur, lane, acc);
                cur = sid;
            }
            float4 v = __ldcs(feat4 + (size_t)r * LANES_F4 + lane);
            acc.x += v.x; acc.y += v.y; acc.z += v.z; acc.w += v.w;
            r += 1;
        }
    }
    red_flush(out, cur, lane, acc);
}

__global__ __launch_bounds__(THREADS_PER_BLOCK, 8)
void segment_sum_kernel(const float4* __restrict__ feat4,
                        const int* __restrict__ seg,
                        float* __restrict__ out,
                        int n_rows, int static_limit, int n_tickets) {
    const int warp_global = (blockIdx.x * WARPS_PER_BLOCK) + (threadIdx.x >> 5);
    const int lane = threadIdx.x & 31;

    // ---- Phase 1: static contiguous range (bulk of the work) ----
    {
        int row0 = warp_global * STATIC_ROWS;
        if (row0 < static_limit) {
            int row_end = row0 + STATIC_ROWS;
            if (row_end > static_limit) row_end = static_limit;
            process_range(feat4, seg, out, row0, row_end, lane);
        }
    }

    // ---- Phase 2: steal 16-row tickets from the tail region ----
    if (n_tickets <= 0) return;
    int t = 0;
    if (lane == 0) t = atomicAdd(&g_ticket, 1);
    t = __shfl_sync(0xffffffffu, t, 0);
    while (t < n_tickets) {
        int tn = 0;
        if (lane == 0) tn = atomicAdd(&g_ticket, 1);   // prefetch next ticket
        int row0 = static_limit + t * TAIL_CHUNK;
        int row_end = row0 + TAIL_CHUNK;
        if (row_end > n_rows) row_end = n_rows;
        process_range(feat4, seg, out, row0, row_end, lane);
        t = __shfl_sync(0xffffffffu, tn, 0);
    }
}

extern "C" void kernel_launch(void* const* d_in, const int* in_sizes, int n_in,
                              void* d_out, int out_size) {
    const float* feat = (const float*)d_in[0];
    const int* seg = (const int*)d_in[1];
    float* out = (float*)d_out;

    const int n_rows = in_sizes[1];            // segment_ids element count

    int static_limit = TOTAL_WARPS * STATIC_ROWS;        // 933,888
    if (static_limit > n_rows) static_limit = n_rows;
    int tail_rows = n_rows - static_limit;
    int n_tickets = (tail_rows + TAIL_CHUNK - 1) / TAIL_CHUNK;

    // 1) zero the (poisoned) output + reset the ticket counter (memset nodes)
    cudaMemsetAsync(out, 0, (size_t)out_size * sizeof(float));
    void* tick_ptr = nullptr;
    cudaGetSymbolAddress(&tick_ptr, g_ticket);
    cudaMemsetAsync(tick_ptr, 0, sizeof(int));

    // 2) hybrid static + stolen-tail segment sum
    segment_sum_kernel<<<PERSISTENT_BLOCKS, THREADS_PER_BLOCK>>>(
        (const float4*)feat, seg, out, n_rows, static_limit, n_tickets);
}